// round 15
// baseline (speedup 1.0000x reference)
#include <cuda_runtime.h>
#include <cuda_fp16.h>
#include <math.h>
#include <stdint.h>

#define E_DIM   1024
#define HID_DIM 4096
#define M_TOT   16384          // B*S = 4*4096
#define NWIN    256            // 4*64 windows of 64 tokens
#define SM_SCALE 0.03125f      // 1024^-0.5
#define LN_EPS  1e-5f

// ---- GEMM tiling: 128x128x64, 4 warps of 64x64, 128 thr, 3-stage, 2 CTA/SM ----
#define BM 128
#define BN 128
#define BK 64
#define SROW 72
#define PL 18432
#define STG 36864
#define NSTAGE 3
#define SMEM_TOTAL (NSTAGE*STG)   // 110592

// ---- attention tiling (R14, kept): 128-wide feature chunks ----
#define ACH   128
#define AR2B  272
#define ATILE (64*AR2B)
#define PROWB 144
#define SSROW 68
#define NCH2  8
#define A_SQ   0
#define A_SK   (2*ATILE)
#define A_SS   (4*ATILE)
#define A_SP   (4*ATILE + 64*SSROW*4)
#define ASMEM  (A_SP + 64*PROWB)           // 96256

// -------- scratch (device globals; no allocation allowed) --------
__device__ __half g_atth[M_TOT * E_DIM];
__device__ __half g_xh  [M_TOT * E_DIM];
__device__ __half g_x1h [M_TOT * E_DIM];
__device__ __half g_hh  [M_TOT * HID_DIM];
__device__ __half g_th  [M_TOT * E_DIM];    // t = x1 + f
__device__ __half g_qkvh[M_TOT * 3 * E_DIM];

__device__ __half g_wqkv[3 * E_DIM * E_DIM];
__device__ float  g_bqkv[3 * E_DIM];
__device__ __half g_w1 [E_DIM * HID_DIM];
__device__ __half g_w2 [HID_DIM * E_DIM];

// ====================================================================
// helpers
// ====================================================================
__device__ __forceinline__ void mma16816(float* c, const uint32_t* a, const uint32_t* b) {
    asm volatile(
        "mma.sync.aligned.m16n8k16.row.col.f32.f16.f16.f32 "
        "{%0,%1,%2,%3},{%4,%5,%6,%7},{%8,%9},{%0,%1,%2,%3};"
        : "+f"(c[0]), "+f"(c[1]), "+f"(c[2]), "+f"(c[3])
        : "r"(a[0]), "r"(a[1]), "r"(a[2]), "r"(a[3]), "r"(b[0]), "r"(b[1]));
}

__device__ __forceinline__ void ldsm4(uint32_t& r0, uint32_t& r1, uint32_t& r2, uint32_t& r3,
                                      uint32_t addr) {
    asm volatile("ldmatrix.sync.aligned.m8n8.x4.shared.b16 {%0,%1,%2,%3},[%4];"
                 : "=r"(r0), "=r"(r1), "=r"(r2), "=r"(r3) : "r"(addr));
}

__device__ __forceinline__ void ldsm4t(uint32_t& r0, uint32_t& r1, uint32_t& r2, uint32_t& r3,
                                       uint32_t addr) {
    asm volatile("ldmatrix.sync.aligned.m8n8.x4.trans.shared.b16 {%0,%1,%2,%3},[%4];"
                 : "=r"(r0), "=r"(r1), "=r"(r2), "=r"(r3) : "r"(addr));
}

// ====================================================================
// elementwise convert: X fp32 -> fp16
// ====================================================================
__global__ __launch_bounds__(256) void cvt_kernel(
    const float* __restrict__ X, __half* __restrict__ H, int n4)
{
    int i = blockIdx.x * 256 + threadIdx.x;
    if (i >= n4) return;
    float4 v = ((const float4*)X)[i];
    __half2* Hp = (__half2*)(H + (size_t)i * 4);
    Hp[0] = __floats2half2_rn(v.x, v.y);
    Hp[1] = __floats2half2_rn(v.z, v.w);
}

__global__ void concat_bias_kernel(const float* __restrict__ a, const float* __restrict__ b,
                                   const float* __restrict__ c, float* __restrict__ o)
{
    int i = blockIdx.x * 256 + threadIdx.x;
    if (i >= 3 * E_DIM) return;
    o[i] = (i < E_DIM) ? a[i] : (i < 2 * E_DIM ? b[i - E_DIM] : c[i - 2 * E_DIM]);
}

// ====================================================================
// weight transpose: W[K,N] fp32 -> T[N,K] fp16
// ====================================================================
__device__ __forceinline__ void wtrans_body(
    const float* __restrict__ W, __half* __restrict__ T, int K, int N)
{
    __shared__ float t[32][33];
    const int tx = threadIdx.x, ty = threadIdx.y;
    const int n0 = blockIdx.x * 32, k0 = blockIdx.y * 32;
#pragma unroll
    for (int i = ty; i < 32; i += 8)
        t[i][tx] = W[(size_t)(k0 + i) * N + n0 + tx];
    __syncthreads();
#pragma unroll
    for (int i = ty; i < 32; i += 8)
        T[(size_t)(n0 + i) * K + k0 + tx] = __float2half(t[tx][i]);
}

__global__ __launch_bounds__(256) void wtrans_kernel(
    const float* __restrict__ W, __half* __restrict__ T, int K, int N)
{
    wtrans_body(W, T, K, N);
}

__global__ __launch_bounds__(256) void wtrans_qkv_kernel(
    const float* __restrict__ Wq, const float* __restrict__ Wk,
    const float* __restrict__ Wv, __half* __restrict__ T)
{
    const float* W = (blockIdx.z == 0) ? Wq : (blockIdx.z == 1 ? Wk : Wv);
    wtrans_body(W, T + (size_t)blockIdx.z * E_DIM * E_DIM, E_DIM, E_DIM);
}

// ====================================================================
// GEMM (TN): Ch[M,N] = fp16( A[M,K] @ B[N,K]^T + bias [+relu|+Rh] )
//   128x128x64 tiles, 4 warps of 64x64, 128 threads, 3-stage pipeline.
//   EPI=1: relu.  EPI=2: plain.  EPI=3: + residual Rh.
// ====================================================================
template <int EPI>
__global__ __launch_bounds__(128, 2) void gemm_tn(
    const __half* __restrict__ A, const __half* __restrict__ B,
    const float* __restrict__ bias,
    __half* __restrict__ Ch, const __half* __restrict__ Rh,
    int M, int N, int K)
{
    extern __shared__ __align__(16) char smem_raw[];
    const int tid = threadIdx.x;
    const int bm0 = blockIdx.y * BM;
    const int bn0 = blockIdx.x * BN;
    const int lane = tid & 31, w = tid >> 5;
    const int g = lane >> 2, q4 = lane & 3;
    const int wm = (w >> 1) * 64;     // 0,64
    const int wn = (w & 1) * 64;      // 0,64

    const uint32_t sbase = (uint32_t)__cvta_generic_to_shared(smem_raw);

    const uint32_t aoff = (uint32_t)((wm + (lane & 15)) * (SROW * 2) + (lane >> 4) * 16);
    const uint32_t boff = (uint32_t)((wn + (lane >> 4) * 8 + (lane & 7)) * (SROW * 2)
                                     + ((lane >> 3) & 1) * 16);

    float acc[4][8][4];
#pragma unroll
    for (int i = 0; i < 4; i++)
#pragma unroll
        for (int j = 0; j < 8; j++)
#pragma unroll
            for (int r = 0; r < 4; r++) acc[i][j][r] = 0.f;

    const __half* gp[2] = {A, B};
    const int rb[2] = {bm0, bn0};

    auto load_stage = [&](int s, int k0) {
        uint32_t sb = sbase + s * STG;
#pragma unroll
        for (int p = 0; p < 2; p++) {
#pragma unroll
            for (int t = 0; t < 8; t++) {
                int i = tid + t * 128;             // 0..1023
                int row = i >> 3, cc = i & 7;
                uint32_t sa = sb + p * PL + (uint32_t)(row * SROW + cc * 8) * 2;
                const void* gptr = gp[p] + (size_t)(rb[p] + row) * K + k0 + cc * 8;
                asm volatile("cp.async.cg.shared.global [%0],[%1],16;" :: "r"(sa), "l"(gptr));
            }
        }
        asm volatile("cp.async.commit_group;");
    };

    const int KT = K / BK;
    load_stage(0, 0);
    load_stage(1, BK);

    for (int kt = 0; kt < KT; kt++) {
        const int s = kt % NSTAGE;
        if (kt < KT - 1) asm volatile("cp.async.wait_group 1;");
        else             asm volatile("cp.async.wait_group 0;");
        __syncthreads();
        if (kt + 2 < KT) load_stage((kt + 2) % NSTAGE, (kt + 2) * BK);

        const uint32_t stg = sbase + s * STG;

#pragma unroll
        for (int ks = 0; ks < 4; ks++) {
            const uint32_t ka = stg + ks * 32 + aoff;
            const uint32_t kb = stg + PL + ks * 32 + boff;

            uint32_t bfr[8][2];
#pragma unroll
            for (int u = 0; u < 4; u++)
                ldsm4(bfr[2 * u][0], bfr[2 * u][1], bfr[2 * u + 1][0], bfr[2 * u + 1][1],
                      kb + u * 16 * (SROW * 2));

            uint32_t afr[4][4];
#pragma unroll
            for (int tm = 0; tm < 4; tm++)
                ldsm4(afr[tm][0], afr[tm][1], afr[tm][2], afr[tm][3], ka + tm * 16 * (SROW * 2));

#pragma unroll
            for (int tm = 0; tm < 4; tm++)
#pragma unroll
                for (int tn = 0; tn < 8; tn++)
                    mma16816(acc[tm][tn], afr[tm], bfr[tn]);
        }
    }

    // epilogue
#pragma unroll
    for (int tm = 0; tm < 4; tm++) {
#pragma unroll
        for (int tn = 0; tn < 8; tn++) {
            int r0 = bm0 + wm + tm * 16 + g;
            int col = bn0 + wn + tn * 8 + q4 * 2;
            float b0 = bias[col], b1 = bias[col + 1];
            float v00 = acc[tm][tn][0] + b0, v01 = acc[tm][tn][1] + b1;
            float v10 = acc[tm][tn][2] + b0, v11 = acc[tm][tn][3] + b1;
            if (EPI == 1) {
                v00 = fmaxf(v00, 0.f); v01 = fmaxf(v01, 0.f);
                v10 = fmaxf(v10, 0.f); v11 = fmaxf(v11, 0.f);
            }
            if (EPI == 3) {
                __half2 r0h = *(const __half2*)(Rh + (size_t)r0 * N + col);
                __half2 r1h = *(const __half2*)(Rh + (size_t)(r0 + 8) * N + col);
                v00 += __low2float(r0h); v01 += __high2float(r0h);
                v10 += __low2float(r1h); v11 += __high2float(r1h);
            }
            *(__half2*)(Ch + (size_t)r0 * N + col)       = __floats2half2_rn(v00, v01);
            *(__half2*)(Ch + (size_t)(r0 + 8) * N + col) = __floats2half2_rn(v10, v11);
        }
    }
}

// ====================================================================
// MMA window attention (R14), 128-wide feature chunks, dynamic smem.
// ====================================================================
__global__ __launch_bounds__(256) void attn_mma_kernel(
    const __half* __restrict__ QKV, __half* __restrict__ O)
{
    extern __shared__ __align__(16) char asmem[];
    __half* sP = (__half*)(asmem + A_SP);
    float*  sS = (float*)(asmem + A_SS);

    const int tid = threadIdx.x;
    const int lane = tid & 31, w = tid >> 5;
    const int tok0 = blockIdx.x * 64;
    const int m0 = (w >> 1) * 16;
    const int n0 = (w & 1) * 32;
    const int g = lane >> 2, q4 = lane & 3;

    const uint32_t sb  = (uint32_t)__cvta_generic_to_shared(asmem);
    const uint32_t sQb = sb + A_SQ;
    const uint32_t sKb = sb + A_SK;
    const uint32_t sPb = sb + A_SP;

    const uint32_t aoff = (uint32_t)((m0 + (lane & 15)) * AR2B + (lane >> 4) * 16);
    const uint32_t boff = (uint32_t)((n0 + (lane >> 4) * 8 + (lane & 7)) * AR2B
                                     + ((lane >> 3) & 1) * 16);
    const uint32_t toff = (uint32_t)((lane & 15) * AR2B + n0 * 2 + (lane >> 4) * 16);
    const uint32_t poff = (uint32_t)((m0 + (lane & 15)) * PROWB + (lane >> 4) * 16);

    auto cpa_tile = [&](uint32_t dstb, int seg, int c0) {
#pragma unroll
        for (int t = 0; t < 4; t++) {
            int i = tid + t * 256;
            int row = i >> 4, cc = i & 15;
            uint32_t sa = dstb + (uint32_t)(row * AR2B + cc * 16);
            const void* src = QKV + (size_t)(tok0 + row) * 3072 + seg + c0 + cc * 8;
            asm volatile("cp.async.cg.shared.global [%0],[%1],16;" :: "r"(sa), "l"(src));
        }
    };

    // ---- phase 1: S = Q K^T ----
    float accs[4][4];
#pragma unroll
    for (int i = 0; i < 4; i++)
#pragma unroll
        for (int r = 0; r < 4; r++) accs[i][r] = 0.f;

    cpa_tile(sQb, 0, 0);
    cpa_tile(sKb, E_DIM, 0);
    asm volatile("cp.async.commit_group;");

    for (int c = 0; c < NCH2; c++) {
        const uint32_t qb = sQb + (c & 1) * ATILE;
        const uint32_t kb = sKb + (c & 1) * ATILE;
        if (c + 1 < NCH2) {
            cpa_tile(sQb + ((c + 1) & 1) * ATILE, 0, (c + 1) * ACH);
            cpa_tile(sKb + ((c + 1) & 1) * ATILE, E_DIM, (c + 1) * ACH);
            asm volatile("cp.async.commit_group;");
            asm volatile("cp.async.wait_group 1;");
        } else {
            asm volatile("cp.async.wait_group 0;");
        }
        __syncthreads();
#pragma unroll
        for (int ks = 0; ks < 8; ks++) {
            uint32_t afr[4], bfr[4][2];
            ldsm4(afr[0], afr[1], afr[2], afr[3], qb + ks * 32 + aoff);
            ldsm4(bfr[0][0], bfr[0][1], bfr[1][0], bfr[1][1], kb + ks * 32 + boff);
            ldsm4(bfr[2][0], bfr[2][1], bfr[3][0], bfr[3][1], kb + ks * 32 + boff + 16 * AR2B);
#pragma unroll
            for (int tn = 0; tn < 4; tn++)
                mma16816(accs[tn], afr, bfr[tn]);
        }
        __syncthreads();
    }

#pragma unroll
    for (int tn = 0; tn < 4; tn++) {
        int col = n0 + tn * 8 + q4 * 2;
        *(float2*)(&sS[(m0 + g) * SSROW + col])     = make_float2(accs[tn][0] * SM_SCALE, accs[tn][1] * SM_SCALE);
        *(float2*)(&sS[(m0 + g + 8) * SSROW + col]) = make_float2(accs[tn][2] * SM_SCALE, accs[tn][3] * SM_SCALE);
    }
    __syncthreads();

    // ---- phase 2: softmax ----
    for (int r = w * 8; r < w * 8 + 8; r++) {
        float v0 = sS[r * SSROW + lane];
        float v1 = sS[r * SSROW + 32 + lane];
        float m = fmaxf(v0, v1);
#pragma unroll
        for (int o = 16; o > 0; o >>= 1)
            m = fmaxf(m, __shfl_xor_sync(0xffffffffu, m, o));
        float e0 = __expf(v0 - m), e1 = __expf(v1 - m);
        float s = e0 + e1;
#pragma unroll
        for (int o = 16; o > 0; o >>= 1)
            s += __shfl_xor_sync(0xffffffffu, s, o);
        float inv = 1.0f / s;
        sS[r * SSROW + lane]      = e0 * inv;
        sS[r * SSROW + 32 + lane] = e1 * inv;
    }
    __syncthreads();

#pragma unroll
    for (int i = 0; i < 16; i++) {
        int flat = tid * 16 + i;
        int r = flat >> 6, cc = flat & 63;
        sP[r * (PROWB / 2) + cc] = __float2half(sS[r * SSROW + cc]);
    }
    __syncthreads();

    // ---- phase 3: O = P @ V ----
    cpa_tile(sKb, 2 * E_DIM, 0);
    asm volatile("cp.async.commit_group;");

    for (int c = 0; c < NCH2; c++) {
        const uint32_t vb = sKb + (c & 1) * ATILE;
        if (c + 1 < NCH2) {
            cpa_tile(sKb + ((c + 1) & 1) * ATILE, 2 * E_DIM, (c + 1) * ACH);
            asm volatile("cp.async.commit_group;");
            asm volatile("cp.async.wait_group 1;");
        } else {
            asm volatile("cp.async.wait_group 0;");
        }
        __syncthreads();
        float acco[2][4][4];
#pragma unroll
        for (int h = 0; h < 2; h++)
#pragma unroll
            for (int i = 0; i < 4; i++)
#pragma unroll
                for (int r = 0; r < 4; r++) acco[h][i][r] = 0.f;
#pragma unroll
        for (int ks = 0; ks < 4; ks++) {
            uint32_t afr[4];
            ldsm4(afr[0], afr[1], afr[2], afr[3], sPb + ks * 32 + poff);
#pragma unroll
            for (int h = 0; h < 2; h++) {
                uint32_t bfr[4][2];
                uint32_t base = vb + (uint32_t)(ks * 16) * AR2B + toff + h * 128;
                ldsm4t(bfr[0][0], bfr[0][1], bfr[1][0], bfr[1][1], base);
                ldsm4t(bfr[2][0], bfr[2][1], bfr[3][0], bfr[3][1], base + 32);
#pragma unroll
                for (int tn = 0; tn < 4; tn++)
                    mma16816(acco[h][tn], afr, bfr[tn]);
            }
        }
#pragma unroll
        for (int h = 0; h < 2; h++)
#pragma unroll
            for (int tn = 0; tn < 4; tn++) {
                int col = c * ACH + h * 64 + n0 + tn * 8 + q4 * 2;
                *(__half2*)(O + (size_t)(tok0 + m0 + g) * E_DIM + col)     = __floats2half2_rn(acco[h][tn][0], acco[h][tn][1]);
                *(__half2*)(O + (size_t)(tok0 + m0 + g + 8) * E_DIM + col) = __floats2half2_rn(acco[h][tn][2], acco[h][tn][3]);
            }
        __syncthreads();
    }
}

// ====================================================================
// LN1: Yh = fp16( LayerNorm(Xh + R) * g + b ),  Xh fp16, R fp16
// ====================================================================
__global__ __launch_bounds__(256) void add_ln1_kernel(
    const __half* __restrict__ Xh, const __half* __restrict__ R,
    const float* __restrict__ g, const float* __restrict__ b,
    __half* __restrict__ Yh)
{
    const size_t off = (size_t)blockIdx.x * E_DIM;
    const int tid = threadIdx.x;
    const int c0 = tid * 4;
    __half2 x0 = *(const __half2*)(Xh + off + c0);
    __half2 x1 = *(const __half2*)(Xh + off + c0 + 2);
    __half2 r0 = *(const __half2*)(R + off + c0);
    __half2 r1 = *(const __half2*)(R + off + c0 + 2);
    float v[4];
    v[0] = __low2float(x0) + __low2float(r0);
    v[1] = __high2float(x0) + __high2float(r0);
    v[2] = __low2float(x1) + __low2float(r1);
    v[3] = __high2float(x1) + __high2float(r1);
    float s = v[0] + v[1] + v[2] + v[3];
    float s2 = v[0]*v[0] + v[1]*v[1] + v[2]*v[2] + v[3]*v[3];
#pragma unroll
    for (int o = 16; o > 0; o >>= 1) {
        s  += __shfl_xor_sync(0xffffffffu, s,  o);
        s2 += __shfl_xor_sync(0xffffffffu, s2, o);
    }
    __shared__ float rs[8], rs2[8];
    __shared__ float s_mean, s_rstd;
    const int lane = tid & 31, wrp = tid >> 5;
    if (lane == 0) { rs[wrp] = s; rs2[wrp] = s2; }
    __syncthreads();
    if (tid == 0) {
        float a = 0.f, a2 = 0.f;
#pragma unroll
        for (int i = 0; i < 8; i++) { a += rs[i]; a2 += rs2[i]; }
        float mean = a * (1.0f / E_DIM);
        float var  = a2 * (1.0f / E_DIM) - mean * mean;
        s_mean = mean; s_rstd = rsqrtf(var + LN_EPS);
    }
    __syncthreads();
    const float mean = s_mean, rstd = s_rstd;
    float4 gg = *(const float4*)(g + c0);
    float4 bb = *(const float4*)(b + c0);
    float y0 = (v[0] - mean) * rstd * gg.x + bb.x;
    float y1 = (v[1] - mean) * rstd * gg.y + bb.y;
    float y2 = (v[2] - mean) * rstd * gg.z + bb.z;
    float y3 = (v[3] - mean) * rstd * gg.w + bb.w;
    *(__half2*)(Yh + off + c0)     = __floats2half2_rn(y0, y1);
    *(__half2*)(Yh + off + c0 + 2) = __floats2half2_rn(y2, y3);
}

// ====================================================================
// LN2: Y = LayerNorm(Th) * g + b
// ====================================================================
__global__ __launch_bounds__(256) void ln2_kernel(
    const __half* __restrict__ Th,
    const float* __restrict__ g, const float* __restrict__ b,
    float* __restrict__ Y)
{
    const size_t off = (size_t)blockIdx.x * E_DIM;
    const int tid = threadIdx.x;
    const int c0 = tid * 4;
    __half2 t0 = *(const __half2*)(Th + off + c0);
    __half2 t1 = *(const __half2*)(Th + off + c0 + 2);
    float v[4];
    v[0] = __low2float(t0); v[1] = __high2float(t0);
    v[2] = __low2float(t1); v[3] = __high2float(t1);
    float s = v[0] + v[1] + v[2] + v[3];
    float s2 = v[0]*v[0] + v[1]*v[1] + v[2]*v[2] + v[3]*v[3];
#pragma unroll
    for (int o = 16; o > 0; o >>= 1) {
        s  += __shfl_xor_sync(0xffffffffu, s,  o);
        s2 += __shfl_xor_sync(0xffffffffu, s2, o);
    }
    __shared__ float rs[8], rs2[8];
    __shared__ float s_mean, s_rstd;
    const int lane = tid & 31, wrp = tid >> 5;
    if (lane == 0) { rs[wrp] = s; rs2[wrp] = s2; }
    __syncthreads();
    if (tid == 0) {
        float a = 0.f, a2 = 0.f;
#pragma unroll
        for (int i = 0; i < 8; i++) { a += rs[i]; a2 += rs2[i]; }
        float mean = a * (1.0f / E_DIM);
        float var  = a2 * (1.0f / E_DIM) - mean * mean;
        s_mean = mean; s_rstd = rsqrtf(var + LN_EPS);
    }
    __syncthreads();
    const float mean = s_mean, rstd = s_rstd;
    float4 gg = *(const float4*)(g + c0);
    float4 bb = *(const float4*)(b + c0);
    float4 y;
    y.x = (v[0] - mean) * rstd * gg.x + bb.x;
    y.y = (v[1] - mean) * rstd * gg.y + bb.y;
    y.z = (v[2] - mean) * rstd * gg.z + bb.z;
    y.w = (v[3] - mean) * rstd * gg.w + bb.w;
    *(float4*)(Y + off + c0) = y;
}

// ====================================================================
extern "C" void kernel_launch(void* const* d_in, const int* in_sizes, int n_in,
                              void* d_out, int out_size)
{
    (void)in_sizes; (void)n_in; (void)out_size;
    const float* x   = (const float*)d_in[0];
    const float* Wq  = (const float*)d_in[1];
    const float* bq  = (const float*)d_in[2];
    const float* Wk  = (const float*)d_in[3];
    const float* bk  = (const float*)d_in[4];
    const float* Wv  = (const float*)d_in[5];
    const float* bv  = (const float*)d_in[6];
    const float* g1  = (const float*)d_in[7];
    const float* be1 = (const float*)d_in[8];
    const float* W1  = (const float*)d_in[9];
    const float* b1  = (const float*)d_in[10];
    const float* W2  = (const float*)d_in[11];
    const float* b2  = (const float*)d_in[12];
    const float* g2  = (const float*)d_in[13];
    const float* be2 = (const float*)d_in[14];
    float* out = (float*)d_out;

    float* bqkv;
    cudaGetSymbolAddress((void**)&bqkv, g_bqkv);

    __half *atth, *xh, *x1h, *hh, *th, *qkvh, *wqkv, *w1, *w2;
    cudaGetSymbolAddress((void**)&atth, g_atth);
    cudaGetSymbolAddress((void**)&xh,   g_xh);
    cudaGetSymbolAddress((void**)&x1h,  g_x1h);
    cudaGetSymbolAddress((void**)&hh,   g_hh);
    cudaGetSymbolAddress((void**)&th,   g_th);
    cudaGetSymbolAddress((void**)&qkvh, g_qkvh);
    cudaGetSymbolAddress((void**)&wqkv, g_wqkv);
    cudaGetSymbolAddress((void**)&w1,   g_w1);
    cudaGetSymbolAddress((void**)&w2,   g_w2);

    cudaFuncSetAttribute(gemm_tn<1>, cudaFuncAttributeMaxDynamicSharedMemorySize, SMEM_TOTAL);
    cudaFuncSetAttribute(gemm_tn<2>, cudaFuncAttributeMaxDynamicSharedMemorySize, SMEM_TOTAL);
    cudaFuncSetAttribute(gemm_tn<3>, cudaFuncAttributeMaxDynamicSharedMemorySize, SMEM_TOTAL);
    cudaFuncSetAttribute(attn_mma_kernel, cudaFuncAttributeMaxDynamicSharedMemorySize, ASMEM);

    dim3 gblk(128);
    dim3 blk(256);
    dim3 tblk(32, 8);

    // operand prep
    cvt_kernel<<<(M_TOT * E_DIM / 4 + 255) / 256, blk>>>(x, xh, M_TOT * E_DIM / 4);
    wtrans_qkv_kernel<<<dim3(E_DIM / 32, E_DIM / 32, 3), tblk>>>(Wq, Wk, Wv, wqkv);
    concat_bias_kernel<<<(3 * E_DIM + 255) / 256, blk>>>(bq, bk, bv, bqkv);
    wtrans_kernel<<<dim3(HID_DIM / 32, E_DIM / 32), tblk>>>(W1, w1, E_DIM, HID_DIM);
    wtrans_kernel<<<dim3(E_DIM / 32, HID_DIM / 32), tblk>>>(W2, w2, HID_DIM, E_DIM);

    // fused QKV projection -> fp16 [M, 3072]
    dim3 grid_qkv(3 * E_DIM / BN, M_TOT / BM);   // (24, 128)
    gemm_tn<2><<<grid_qkv, gblk, SMEM_TOTAL>>>(xh, wqkv, bqkv, qkvh, nullptr, M_TOT, 3 * E_DIM, E_DIM);

    // per-window MMA attention -> fp16 att
    attn_mma_kernel<<<NWIN, blk, ASMEM>>>(qkvh, atth);

    // x1h = fp16(LN(x + att))
    add_ln1_kernel<<<M_TOT, blk>>>(xh, atth, g1, be1, x1h);

    // FFN1: h = relu(x1 @ W1 + b1), fp16
    dim3 grid_f1(HID_DIM / BN, M_TOT / BM);      // (32, 128)
    gemm_tn<1><<<grid_f1, gblk, SMEM_TOTAL>>>(x1h, w1, b1, hh, nullptr, M_TOT, HID_DIM, E_DIM);

    // FFN2 + residual: th = fp16(h @ W2 + b2 + x1)
    dim3 grid_f2(E_DIM / BN, M_TOT / BM);        // (8, 128)
    gemm_tn<3><<<grid_f2, gblk, SMEM_TOTAL>>>(hh, w2, b2, th, x1h, M_TOT, E_DIM, HID_DIM);

    // out = LN(th)
    ln2_kernel<<<M_TOT, blk>>>(th, g2, be2, out);
}

// round 16
// speedup vs baseline: 1.0815x; 1.0815x over previous
#include <cuda_runtime.h>
#include <cuda_fp16.h>
#include <math.h>
#include <stdint.h>

#define E_DIM   1024
#define HID_DIM 4096
#define M_TOT   16384          // B*S = 4*4096
#define NWIN    256            // 4*64 windows of 64 tokens
#define SM_SCALE 0.03125f      // 1024^-0.5
#define LN_EPS  1e-5f

// ---- GEMM tiling (frozen best): 128x128x64, 8 warps of 64x32, 3-stage, 2 CTA/SM ----
#define BM 128
#define BN 128
#define BK 64
#define SROW 72
#define PL 18432
#define STG 36864
#define NSTAGE 3
#define SMEM_TOTAL (NSTAGE*STG)   // 110592

// ---- attention tiling: 128-wide feature chunks ----
#define ACH   128
#define AR2B  272
#define ATILE (64*AR2B)
#define PROWB 144
#define SSROW 68
#define NCH2  8
#define A_SQ   0
#define A_SK   (2*ATILE)
#define A_SS   (4*ATILE)
#define A_SP   (4*ATILE + 64*SSROW*4)
#define ASMEM  (A_SP + 64*PROWB)           // 96256

// ---- fused prep kernel block ranges ----
#define NB_CVT   16384                     // M_TOT*E_DIM/4/256
#define NB_WQKV  3072                      // 3 * 32*32
#define NB_W1    4096                      // 128 * 32
#define NB_W2    4096                      // 32 * 128
#define NB_BIAS  12                        // 3072/256
#define NB_PREP  (NB_CVT+NB_WQKV+NB_W1+NB_W2+NB_BIAS)

// -------- scratch (device globals; no allocation allowed) --------
__device__ __half g_atth[M_TOT * E_DIM];
__device__ __half g_xh  [M_TOT * E_DIM];
__device__ __half g_x1h [M_TOT * E_DIM];
__device__ __half g_hh  [M_TOT * HID_DIM];
__device__ __half g_th  [M_TOT * E_DIM];    // t = x1 + f
__device__ __half g_qkvh[M_TOT * 3 * E_DIM];

__device__ __half g_wqkv[3 * E_DIM * E_DIM];
__device__ float  g_bqkv[3 * E_DIM];
__device__ __half g_w1 [E_DIM * HID_DIM];
__device__ __half g_w2 [HID_DIM * E_DIM];

// ====================================================================
// helpers
// ====================================================================
__device__ __forceinline__ void mma16816(float* c, const uint32_t* a, const uint32_t* b) {
    asm volatile(
        "mma.sync.aligned.m16n8k16.row.col.f32.f16.f16.f32 "
        "{%0,%1,%2,%3},{%4,%5,%6,%7},{%8,%9},{%0,%1,%2,%3};"
        : "+f"(c[0]), "+f"(c[1]), "+f"(c[2]), "+f"(c[3])
        : "r"(a[0]), "r"(a[1]), "r"(a[2]), "r"(a[3]), "r"(b[0]), "r"(b[1]));
}

__device__ __forceinline__ void ldsm4(uint32_t& r0, uint32_t& r1, uint32_t& r2, uint32_t& r3,
                                      uint32_t addr) {
    asm volatile("ldmatrix.sync.aligned.m8n8.x4.shared.b16 {%0,%1,%2,%3},[%4];"
                 : "=r"(r0), "=r"(r1), "=r"(r2), "=r"(r3) : "r"(addr));
}

__device__ __forceinline__ void ldsm4t(uint32_t& r0, uint32_t& r1, uint32_t& r2, uint32_t& r3,
                                       uint32_t addr) {
    asm volatile("ldmatrix.sync.aligned.m8n8.x4.trans.shared.b16 {%0,%1,%2,%3},[%4];"
                 : "=r"(r0), "=r"(r1), "=r"(r2), "=r"(r3) : "r"(addr));
}

// ====================================================================
// fused prep: cvt(x->xh) | wtrans q/k/v | wtrans W1 | wtrans W2 | bias
// ====================================================================
__device__ __forceinline__ void wtrans_tile(
    const float* __restrict__ W, __half* __restrict__ T,
    int K, int N, int n0, int k0, int tid)
{
    __shared__ float t[32][33];
    const int tx = tid & 31, ty = tid >> 5;
#pragma unroll
    for (int i = ty; i < 32; i += 8)
        t[i][tx] = W[(size_t)(k0 + i) * N + n0 + tx];
    __syncthreads();
#pragma unroll
    for (int i = ty; i < 32; i += 8)
        T[(size_t)(n0 + i) * K + k0 + tx] = __float2half(t[tx][i]);
}

__global__ __launch_bounds__(256) void prep_kernel(
    const float* __restrict__ x, __half* __restrict__ xh,
    const float* __restrict__ Wq, const float* __restrict__ Wk,
    const float* __restrict__ Wv, __half* __restrict__ wqkv,
    const float* __restrict__ W1, __half* __restrict__ w1,
    const float* __restrict__ W2, __half* __restrict__ w2,
    const float* __restrict__ bq, const float* __restrict__ bk,
    const float* __restrict__ bv, float* __restrict__ bqkv)
{
    int b = blockIdx.x;
    const int tid = threadIdx.x;
    if (b < NB_CVT) {
        int i = b * 256 + tid;
        float4 v = ((const float4*)x)[i];
        __half2* Hp = (__half2*)(xh + (size_t)i * 4);
        Hp[0] = __floats2half2_rn(v.x, v.y);
        Hp[1] = __floats2half2_rn(v.z, v.w);
        return;
    }
    b -= NB_CVT;
    if (b < NB_WQKV) {
        int z = b / 1024, r = b % 1024;
        const float* W = (z == 0) ? Wq : (z == 1 ? Wk : Wv);
        wtrans_tile(W, wqkv + (size_t)z * E_DIM * E_DIM, E_DIM, E_DIM,
                    (r & 31) * 32, (r >> 5) * 32, tid);
        return;
    }
    b -= NB_WQKV;
    if (b < NB_W1) {
        // W1[K=E, N=HID] -> w1[N,K]; 128 n-tiles x 32 k-tiles
        wtrans_tile(W1, w1, E_DIM, HID_DIM, (b & 127) * 32, (b >> 7) * 32, tid);
        return;
    }
    b -= NB_W1;
    if (b < NB_W2) {
        // W2[K=HID, N=E] -> w2[N,K]; 32 n-tiles x 128 k-tiles
        wtrans_tile(W2, w2, HID_DIM, E_DIM, (b & 31) * 32, (b >> 5) * 32, tid);
        return;
    }
    b -= NB_W2;
    {
        int i = b * 256 + tid;
        if (i < 3 * E_DIM)
            bqkv[i] = (i < E_DIM) ? bq[i] : (i < 2 * E_DIM ? bk[i - E_DIM] : bv[i - 2 * E_DIM]);
    }
}

// ====================================================================
// GEMM (TN): Ch[M,N] = fp16( A[M,K] @ B[N,K]^T + bias [+relu|+Rh] )
//   128x128x64 tiles, 8 warps of 64x32, 3-stage cp.async pipeline.
//   EPI=1: relu.  EPI=2: plain.  EPI=3: + residual Rh.
// ====================================================================
template <int EPI>
__global__ __launch_bounds__(256, 2) void gemm_tn(
    const __half* __restrict__ A, const __half* __restrict__ B,
    const float* __restrict__ bias,
    __half* __restrict__ Ch, const __half* __restrict__ Rh,
    int M, int N, int K)
{
    extern __shared__ __align__(16) char smem_raw[];
    const int tid = threadIdx.x;
    const int bm0 = blockIdx.y * BM;
    const int bn0 = blockIdx.x * BN;
    const int lane = tid & 31, w = tid >> 5;
    const int g = lane >> 2, q4 = lane & 3;
    const int wm = (w >> 2) * 64;
    const int wn = (w & 3) * 32;

    const uint32_t sbase = (uint32_t)__cvta_generic_to_shared(smem_raw);

    const uint32_t aoff = (uint32_t)((wm + (lane & 15)) * (SROW * 2) + (lane >> 4) * 16);
    const uint32_t boff = (uint32_t)((wn + (lane >> 4) * 8 + (lane & 7)) * (SROW * 2)
                                     + ((lane >> 3) & 1) * 16);

    float acc[4][4][4];
#pragma unroll
    for (int i = 0; i < 4; i++)
#pragma unroll
        for (int j = 0; j < 4; j++)
#pragma unroll
            for (int r = 0; r < 4; r++) acc[i][j][r] = 0.f;

    const __half* gp[2] = {A, B};
    const int rb[2] = {bm0, bn0};

    auto load_stage = [&](int s, int k0) {
        uint32_t sb = sbase + s * STG;
#pragma unroll
        for (int p = 0; p < 2; p++) {
#pragma unroll
            for (int t = 0; t < 4; t++) {
                int i = tid + t * 256;
                int row = i >> 3, cc = i & 7;
                uint32_t sa = sb + p * PL + (uint32_t)(row * SROW + cc * 8) * 2;
                const void* gptr = gp[p] + (size_t)(rb[p] + row) * K + k0 + cc * 8;
                asm volatile("cp.async.cg.shared.global [%0],[%1],16;" :: "r"(sa), "l"(gptr));
            }
        }
        asm volatile("cp.async.commit_group;");
    };

    const int KT = K / BK;
    load_stage(0, 0);
    load_stage(1, BK);

    for (int kt = 0; kt < KT; kt++) {
        const int s = kt % NSTAGE;
        if (kt < KT - 1) asm volatile("cp.async.wait_group 1;");
        else             asm volatile("cp.async.wait_group 0;");
        __syncthreads();
        if (kt + 2 < KT) load_stage((kt + 2) % NSTAGE, (kt + 2) * BK);

        const uint32_t stg = sbase + s * STG;

#pragma unroll
        for (int ks = 0; ks < 4; ks++) {
            const uint32_t ka = stg + ks * 32 + aoff;
            const uint32_t kb = stg + PL + ks * 32 + boff;

            uint32_t bfr[4][2];
            ldsm4(bfr[0][0], bfr[0][1], bfr[1][0], bfr[1][1], kb);
            ldsm4(bfr[2][0], bfr[2][1], bfr[3][0], bfr[3][1], kb + 16 * (SROW * 2));

            uint32_t afr[4][4];
#pragma unroll
            for (int tm = 0; tm < 4; tm++)
                ldsm4(afr[tm][0], afr[tm][1], afr[tm][2], afr[tm][3], ka + tm * 16 * (SROW * 2));

#pragma unroll
            for (int tm = 0; tm < 4; tm++)
#pragma unroll
                for (int tn = 0; tn < 4; tn++)
                    mma16816(acc[tm][tn], afr[tm], bfr[tn]);
        }
    }

#pragma unroll
    for (int tm = 0; tm < 4; tm++) {
#pragma unroll
        for (int tn = 0; tn < 4; tn++) {
            int r0 = bm0 + wm + tm * 16 + g;
            int col = bn0 + wn + tn * 8 + q4 * 2;
            float b0 = bias[col], b1 = bias[col + 1];
            float v00 = acc[tm][tn][0] + b0, v01 = acc[tm][tn][1] + b1;
            float v10 = acc[tm][tn][2] + b0, v11 = acc[tm][tn][3] + b1;
            if (EPI == 1) {
                v00 = fmaxf(v00, 0.f); v01 = fmaxf(v01, 0.f);
                v10 = fmaxf(v10, 0.f); v11 = fmaxf(v11, 0.f);
            }
            if (EPI == 3) {
                __half2 r0h = *(const __half2*)(Rh + (size_t)r0 * N + col);
                __half2 r1h = *(const __half2*)(Rh + (size_t)(r0 + 8) * N + col);
                v00 += __low2float(r0h); v01 += __high2float(r0h);
                v10 += __low2float(r1h); v11 += __high2float(r1h);
            }
            *(__half2*)(Ch + (size_t)r0 * N + col)       = __floats2half2_rn(v00, v01);
            *(__half2*)(Ch + (size_t)(r0 + 8) * N + col) = __floats2half2_rn(v10, v11);
        }
    }
}

// ====================================================================
// MMA window attention, 128-wide feature chunks, dynamic smem.
// ====================================================================
__global__ __launch_bounds__(256) void attn_mma_kernel(
    const __half* __restrict__ QKV, __half* __restrict__ O)
{
    extern __shared__ __align__(16) char asmem[];
    __half* sP = (__half*)(asmem + A_SP);
    float*  sS = (float*)(asmem + A_SS);

    const int tid = threadIdx.x;
    const int lane = tid & 31, w = tid >> 5;
    const int tok0 = blockIdx.x * 64;
    const int m0 = (w >> 1) * 16;
    const int n0 = (w & 1) * 32;
    const int g = lane >> 2, q4 = lane & 3;

    const uint32_t sb  = (uint32_t)__cvta_generic_to_shared(asmem);
    const uint32_t sQb = sb + A_SQ;
    const uint32_t sKb = sb + A_SK;
    const uint32_t sPb = sb + A_SP;

    const uint32_t aoff = (uint32_t)((m0 + (lane & 15)) * AR2B + (lane >> 4) * 16);
    const uint32_t boff = (uint32_t)((n0 + (lane >> 4) * 8 + (lane & 7)) * AR2B
                                     + ((lane >> 3) & 1) * 16);
    const uint32_t toff = (uint32_t)((lane & 15) * AR2B + n0 * 2 + (lane >> 4) * 16);
    const uint32_t poff = (uint32_t)((m0 + (lane & 15)) * PROWB + (lane >> 4) * 16);

    auto cpa_tile = [&](uint32_t dstb, int seg, int c0) {
#pragma unroll
        for (int t = 0; t < 4; t++) {
            int i = tid + t * 256;
            int row = i >> 4, cc = i & 15;
            uint32_t sa = dstb + (uint32_t)(row * AR2B + cc * 16);
            const void* src = QKV + (size_t)(tok0 + row) * 3072 + seg + c0 + cc * 8;
            asm volatile("cp.async.cg.shared.global [%0],[%1],16;" :: "r"(sa), "l"(src));
        }
    };

    // ---- phase 1: S = Q K^T ----
    float accs[4][4];
#pragma unroll
    for (int i = 0; i < 4; i++)
#pragma unroll
        for (int r = 0; r < 4; r++) accs[i][r] = 0.f;

    cpa_tile(sQb, 0, 0);
    cpa_tile(sKb, E_DIM, 0);
    asm volatile("cp.async.commit_group;");

    for (int c = 0; c < NCH2; c++) {
        const uint32_t qb = sQb + (c & 1) * ATILE;
        const uint32_t kb = sKb + (c & 1) * ATILE;
        if (c + 1 < NCH2) {
            cpa_tile(sQb + ((c + 1) & 1) * ATILE, 0, (c + 1) * ACH);
            cpa_tile(sKb + ((c + 1) & 1) * ATILE, E_DIM, (c + 1) * ACH);
            asm volatile("cp.async.commit_group;");
            asm volatile("cp.async.wait_group 1;");
        } else {
            asm volatile("cp.async.wait_group 0;");
        }
        __syncthreads();
#pragma unroll
        for (int ks = 0; ks < 8; ks++) {
            uint32_t afr[4], bfr[4][2];
            ldsm4(afr[0], afr[1], afr[2], afr[3], qb + ks * 32 + aoff);
            ldsm4(bfr[0][0], bfr[0][1], bfr[1][0], bfr[1][1], kb + ks * 32 + boff);
            ldsm4(bfr[2][0], bfr[2][1], bfr[3][0], bfr[3][1], kb + ks * 32 + boff + 16 * AR2B);
#pragma unroll
            for (int tn = 0; tn < 4; tn++)
                mma16816(accs[tn], afr, bfr[tn]);
        }
        __syncthreads();
    }

#pragma unroll
    for (int tn = 0; tn < 4; tn++) {
        int col = n0 + tn * 8 + q4 * 2;
        *(float2*)(&sS[(m0 + g) * SSROW + col])     = make_float2(accs[tn][0] * SM_SCALE, accs[tn][1] * SM_SCALE);
        *(float2*)(&sS[(m0 + g + 8) * SSROW + col]) = make_float2(accs[tn][2] * SM_SCALE, accs[tn][3] * SM_SCALE);
    }
    __syncthreads();

    // ---- phase 2: softmax ----
    for (int r = w * 8; r < w * 8 + 8; r++) {
        float v0 = sS[r * SSROW + lane];
        float v1 = sS[r * SSROW + 32 + lane];
        float m = fmaxf(v0, v1);
#pragma unroll
        for (int o = 16; o > 0; o >>= 1)
            m = fmaxf(m, __shfl_xor_sync(0xffffffffu, m, o));
        float e0 = __expf(v0 - m), e1 = __expf(v1 - m);
        float s = e0 + e1;
#pragma unroll
        for (int o = 16; o > 0; o >>= 1)
            s += __shfl_xor_sync(0xffffffffu, s, o);
        float inv = 1.0f / s;
        sS[r * SSROW + lane]      = e0 * inv;
        sS[r * SSROW + 32 + lane] = e1 * inv;
    }
    __syncthreads();

#pragma unroll
    for (int i = 0; i < 16; i++) {
        int flat = tid * 16 + i;
        int r = flat >> 6, cc = flat & 63;
        sP[r * (PROWB / 2) + cc] = __float2half(sS[r * SSROW + cc]);
    }
    __syncthreads();

    // ---- phase 3: O = P @ V ----
    cpa_tile(sKb, 2 * E_DIM, 0);
    asm volatile("cp.async.commit_group;");

    for (int c = 0; c < NCH2; c++) {
        const uint32_t vb = sKb + (c & 1) * ATILE;
        if (c + 1 < NCH2) {
            cpa_tile(sKb + ((c + 1) & 1) * ATILE, 2 * E_DIM, (c + 1) * ACH);
            asm volatile("cp.async.commit_group;");
            asm volatile("cp.async.wait_group 1;");
        } else {
            asm volatile("cp.async.wait_group 0;");
        }
        __syncthreads();
        float acco[2][4][4];
#pragma unroll
        for (int h = 0; h < 2; h++)
#pragma unroll
            for (int i = 0; i < 4; i++)
#pragma unroll
                for (int r = 0; r < 4; r++) acco[h][i][r] = 0.f;
#pragma unroll
        for (int ks = 0; ks < 4; ks++) {
            uint32_t afr[4];
            ldsm4(afr[0], afr[1], afr[2], afr[3], sPb + ks * 32 + poff);
#pragma unroll
            for (int h = 0; h < 2; h++) {
                uint32_t bfr[4][2];
                uint32_t base = vb + (uint32_t)(ks * 16) * AR2B + toff + h * 128;
                ldsm4t(bfr[0][0], bfr[0][1], bfr[1][0], bfr[1][1], base);
                ldsm4t(bfr[2][0], bfr[2][1], bfr[3][0], bfr[3][1], base + 32);
#pragma unroll
                for (int tn = 0; tn < 4; tn++)
                    mma16816(acco[h][tn], afr, bfr[tn]);
            }
        }
#pragma unroll
        for (int h = 0; h < 2; h++)
#pragma unroll
            for (int tn = 0; tn < 4; tn++) {
                int col = c * ACH + h * 64 + n0 + tn * 8 + q4 * 2;
                *(__half2*)(O + (size_t)(tok0 + m0 + g) * E_DIM + col)     = __floats2half2_rn(acco[h][tn][0], acco[h][tn][1]);
                *(__half2*)(O + (size_t)(tok0 + m0 + g + 8) * E_DIM + col) = __floats2half2_rn(acco[h][tn][2], acco[h][tn][3]);
            }
        __syncthreads();
    }
}

// ====================================================================
// LN1: Yh = fp16( LayerNorm(Xh + R) * g + b ),  Xh fp16, R fp16
// ====================================================================
__global__ __launch_bounds__(256) void add_ln1_kernel(
    const __half* __restrict__ Xh, const __half* __restrict__ R,
    const float* __restrict__ g, const float* __restrict__ b,
    __half* __restrict__ Yh)
{
    const size_t off = (size_t)blockIdx.x * E_DIM;
    const int tid = threadIdx.x;
    const int c0 = tid * 4;
    __half2 x0 = *(const __half2*)(Xh + off + c0);
    __half2 x1 = *(const __half2*)(Xh + off + c0 + 2);
    __half2 r0 = *(const __half2*)(R + off + c0);
    __half2 r1 = *(const __half2*)(R + off + c0 + 2);
    float v[4];
    v[0] = __low2float(x0) + __low2float(r0);
    v[1] = __high2float(x0) + __high2float(r0);
    v[2] = __low2float(x1) + __low2float(r1);
    v[3] = __high2float(x1) + __high2float(r1);
    float s = v[0] + v[1] + v[2] + v[3];
    float s2 = v[0]*v[0] + v[1]*v[1] + v[2]*v[2] + v[3]*v[3];
#pragma unroll
    for (int o = 16; o > 0; o >>= 1) {
        s  += __shfl_xor_sync(0xffffffffu, s,  o);
        s2 += __shfl_xor_sync(0xffffffffu, s2, o);
    }
    __shared__ float rs[8], rs2[8];
    __shared__ float s_mean, s_rstd;
    const int lane = tid & 31, wrp = tid >> 5;
    if (lane == 0) { rs[wrp] = s; rs2[wrp] = s2; }
    __syncthreads();
    if (tid == 0) {
        float a = 0.f, a2 = 0.f;
#pragma unroll
        for (int i = 0; i < 8; i++) { a += rs[i]; a2 += rs2[i]; }
        float mean = a * (1.0f / E_DIM);
        float var  = a2 * (1.0f / E_DIM) - mean * mean;
        s_mean = mean; s_rstd = rsqrtf(var + LN_EPS);
    }
    __syncthreads();
    const float mean = s_mean, rstd = s_rstd;
    float4 gg = *(const float4*)(g + c0);
    float4 bb = *(const float4*)(b + c0);
    float y0 = (v[0] - mean) * rstd * gg.x + bb.x;
    float y1 = (v[1] - mean) * rstd * gg.y + bb.y;
    float y2 = (v[2] - mean) * rstd * gg.z + bb.z;
    float y3 = (v[3] - mean) * rstd * gg.w + bb.w;
    *(__half2*)(Yh + off + c0)     = __floats2half2_rn(y0, y1);
    *(__half2*)(Yh + off + c0 + 2) = __floats2half2_rn(y2, y3);
}

// ====================================================================
// LN2: Y = LayerNorm(Th) * g + b
// ====================================================================
__global__ __launch_bounds__(256) void ln2_kernel(
    const __half* __restrict__ Th,
    const float* __restrict__ g, const float* __restrict__ b,
    float* __restrict__ Y)
{
    const size_t off = (size_t)blockIdx.x * E_DIM;
    const int tid = threadIdx.x;
    const int c0 = tid * 4;
    __half2 t0 = *(const __half2*)(Th + off + c0);
    __half2 t1 = *(const __half2*)(Th + off + c0 + 2);
    float v[4];
    v[0] = __low2float(t0); v[1] = __high2float(t0);
    v[2] = __low2float(t1); v[3] = __high2float(t1);
    float s = v[0] + v[1] + v[2] + v[3];
    float s2 = v[0]*v[0] + v[1]*v[1] + v[2]*v[2] + v[3]*v[3];
#pragma unroll
    for (int o = 16; o > 0; o >>= 1) {
        s  += __shfl_xor_sync(0xffffffffu, s,  o);
        s2 += __shfl_xor_sync(0xffffffffu, s2, o);
    }
    __shared__ float rs[8], rs2[8];
    __shared__ float s_mean, s_rstd;
    const int lane = tid & 31, wrp = tid >> 5;
    if (lane == 0) { rs[wrp] = s; rs2[wrp] = s2; }
    __syncthreads();
    if (tid == 0) {
        float a = 0.f, a2 = 0.f;
#pragma unroll
        for (int i = 0; i < 8; i++) { a += rs[i]; a2 += rs2[i]; }
        float mean = a * (1.0f / E_DIM);
        float var  = a2 * (1.0f / E_DIM) - mean * mean;
        s_mean = mean; s_rstd = rsqrtf(var + LN_EPS);
    }
    __syncthreads();
    const float mean = s_mean, rstd = s_rstd;
    float4 gg = *(const float4*)(g + c0);
    float4 bb = *(const float4*)(b + c0);
    float4 y;
    y.x = (v[0] - mean) * rstd * gg.x + bb.x;
    y.y = (v[1] - mean) * rstd * gg.y + bb.y;
    y.z = (v[2] - mean) * rstd * gg.z + bb.z;
    y.w = (v[3] - mean) * rstd * gg.w + bb.w;
    *(float4*)(Y + off + c0) = y;
}

// ====================================================================
extern "C" void kernel_launch(void* const* d_in, const int* in_sizes, int n_in,
                              void* d_out, int out_size)
{
    (void)in_sizes; (void)n_in; (void)out_size;
    const float* x   = (const float*)d_in[0];
    const float* Wq  = (const float*)d_in[1];
    const float* bq  = (const float*)d_in[2];
    const float* Wk  = (const float*)d_in[3];
    const float* bk  = (const float*)d_in[4];
    const float* Wv  = (const float*)d_in[5];
    const float* bv  = (const float*)d_in[6];
    const float* g1  = (const float*)d_in[7];
    const float* be1 = (const float*)d_in[8];
    const float* W1  = (const float*)d_in[9];
    const float* b1  = (const float*)d_in[10];
    const float* W2  = (const float*)d_in[11];
    const float* b2  = (const float*)d_in[12];
    const float* g2  = (const float*)d_in[13];
    const float* be2 = (const float*)d_in[14];
    float* out = (float*)d_out;

    float* bqkv;
    cudaGetSymbolAddress((void**)&bqkv, g_bqkv);

    __half *atth, *xh, *x1h, *hh, *th, *qkvh, *wqkv, *w1, *w2;
    cudaGetSymbolAddress((void**)&atth, g_atth);
    cudaGetSymbolAddress((void**)&xh,   g_xh);
    cudaGetSymbolAddress((void**)&x1h,  g_x1h);
    cudaGetSymbolAddress((void**)&hh,   g_hh);
    cudaGetSymbolAddress((void**)&th,   g_th);
    cudaGetSymbolAddress((void**)&qkvh, g_qkvh);
    cudaGetSymbolAddress((void**)&wqkv, g_wqkv);
    cudaGetSymbolAddress((void**)&w1,   g_w1);
    cudaGetSymbolAddress((void**)&w2,   g_w2);

    cudaFuncSetAttribute(gemm_tn<1>, cudaFuncAttributeMaxDynamicSharedMemorySize, SMEM_TOTAL);
    cudaFuncSetAttribute(gemm_tn<2>, cudaFuncAttributeMaxDynamicSharedMemorySize, SMEM_TOTAL);
    cudaFuncSetAttribute(gemm_tn<3>, cudaFuncAttributeMaxDynamicSharedMemorySize, SMEM_TOTAL);
    cudaFuncSetAttribute(attn_mma_kernel, cudaFuncAttributeMaxDynamicSharedMemorySize, ASMEM);

    dim3 blk(256);

    // fused operand prep: cvt + 5 transposes + bias concat, one launch
    prep_kernel<<<NB_PREP, blk>>>(x, xh, Wq, Wk, Wv, wqkv, W1, w1, W2, w2,
                                  bq, bk, bv, bqkv);

    // fused QKV projection -> fp16 [M, 3072]
    dim3 grid_qkv(3 * E_DIM / BN, M_TOT / BM);   // (24, 128)
    gemm_tn<2><<<grid_qkv, blk, SMEM_TOTAL>>>(xh, wqkv, bqkv, qkvh, nullptr, M_TOT, 3 * E_DIM, E_DIM);

    // per-window MMA attention -> fp16 att
    attn_mma_kernel<<<NWIN, blk, ASMEM>>>(qkvh, atth);

    // x1h = fp16(LN(x + att))
    add_ln1_kernel<<<M_TOT, blk>>>(xh, atth, g1, be1, x1h);

    // FFN1: h = relu(x1 @ W1 + b1), fp16
    dim3 grid_f1(HID_DIM / BN, M_TOT / BM);      // (32, 128)
    gemm_tn<1><<<grid_f1, blk, SMEM_TOTAL>>>(x1h, w1, b1, hh, nullptr, M_TOT, HID_DIM, E_DIM);

    // FFN2 + residual: th = fp16(h @ W2 + b2 + x1)
    dim3 grid_f2(E_DIM / BN, M_TOT / BM);        // (8, 128)
    gemm_tn<3><<<grid_f2, blk, SMEM_TOTAL>>>(hh, w2, b2, th, x1h, M_TOT, E_DIM, HID_DIM);

    // out = LN(th)
    ln2_kernel<<<M_TOT, blk>>>(th, g2, be2, out);
}